// round 3
// baseline (speedup 1.0000x reference)
#include <cuda_runtime.h>
#include <math.h>

#define Bsz 128
#define Nn  512
#define Dd  64
#define KTOP 20
#define FULLMASK 0xFFFFFFFFu
#define NEG_SLOPE 0.2f
#define BN_EPS 1e-5f

typedef unsigned long long ull;

// ---------------- scratch (device globals; no allocations) ----------------
__device__ __align__(16) float g_rst[Bsz*Nn*Dd];   // 16.7 MB
__device__ __align__(16) float g_cos[Nn*Nn];       // 1 MB
__device__ __align__(16) float g_wT[Dd*Dd];        // fc_w transposed: wT[f][d]
__device__ int   g_srcT[Nn*KTOP];                  // srcT[d][j] = src of edge d+512j
__device__ float g_esrc[Nn];
__device__ float g_edst[Nn];
__device__ __align__(16) float g_sum[Dd];
__device__ __align__(16) float g_sumsq[Dd];

// ---------------- f32x2 packed helpers (PTX-only on sm_103a) ---------------
__device__ __forceinline__ ull pack2(float x, float y) {
    ull r; asm("mov.b64 %0, {%1, %2};" : "=l"(r) : "f"(x), "f"(y)); return r;
}
__device__ __forceinline__ void fma2(ull& d, ull a, ull b) {
    asm("fma.rn.f32x2 %0, %1, %2, %0;" : "+l"(d) : "l"(a), "l"(b));
}
__device__ __forceinline__ float2 unpack2(ull v) {
    float2 r; asm("mov.b64 {%0, %1}, %2;" : "=f"(r.x), "=f"(r.y) : "l"(v)); return r;
}

// ---------------- K1: cosine Gram matrix + local norms + zero accums -------
__global__ void k1_cos(const float* __restrict__ emb) {
    __shared__ float At[64*68];
    __shared__ float Bt[64*68];
    __shared__ float rni[64], rnj[64];
    int i0 = blockIdx.y * 64, j0 = blockIdx.x * 64;
    int tid = threadIdx.x;           // 256 threads
    for (int idx = tid; idx < 4096; idx += 256) {
        int r = idx >> 6, k = idx & 63;
        At[k*68 + r] = emb[(i0 + r)*64 + k];
        Bt[k*68 + r] = emb[(j0 + r)*64 + k];
    }
    __syncthreads();
    if (tid < 128) {
        int r = tid & 63;
        const float* T = (tid >= 64) ? Bt : At;
        float s = 0.f;
#pragma unroll
        for (int k = 0; k < 64; ++k) { float v = T[k*68 + r]; s = fmaf(v, v, s); }
        float inv = 1.0f / sqrtf(s);
        if (tid >= 64) rnj[r] = inv; else rni[r] = inv;
    } else if (blockIdx.x == 0 && blockIdx.y == 0 && tid < 256) {
        int t = tid - 128;
        if (t < 64) g_sum[t] = 0.f;
        else if (t < 128) g_sumsq[t - 64] = 0.f;
    }
    __syncthreads();
    int tx = tid & 15, ty = tid >> 4;
    int r0 = ty * 4, c0 = tx * 4;
    float acc[4][4] = {};
#pragma unroll 8
    for (int k = 0; k < 64; ++k) {
        float4 a4 = *(const float4*)&At[k*68 + r0];
        float4 b4 = *(const float4*)&Bt[k*68 + c0];
        float av[4] = {a4.x, a4.y, a4.z, a4.w};
        float bv[4] = {b4.x, b4.y, b4.z, b4.w};
#pragma unroll
        for (int r = 0; r < 4; ++r)
#pragma unroll
            for (int c = 0; c < 4; ++c)
                acc[r][c] = fmaf(av[r], bv[c], acc[r][c]);
    }
    float rj[4];
#pragma unroll
    for (int c = 0; c < 4; ++c) rj[c] = rnj[c0 + c];
#pragma unroll
    for (int r = 0; r < 4; ++r) {
        float ri = rni[r0 + r];
        float4 o;
        o.x = acc[r][0] * ri * rj[0];
        o.y = acc[r][1] * ri * rj[1];
        o.z = acc[r][2] * ri * rj[2];
        o.w = acc[r][3] * ri * rj[3];
        *(float4*)&g_cos[(i0 + r0 + r)*Nn + j0 + c0] = o;
    }
}

// ---------------- K2: per-row top-20 + misc precompute ---------------------
__global__ void k2_topk(const float* __restrict__ emb,
                        const float* __restrict__ attn_w,
                        const float* __restrict__ fc_w) {
    int w    = blockIdx.x * (blockDim.x >> 5) + (threadIdx.x >> 5); // row
    int lane = threadIdx.x & 31;
    const float* row = g_cos + w * Nn;
    float v[16];
#pragma unroll
    for (int t = 0; t < 16; ++t) v[t] = row[t*32 + lane];
    float bv = v[0]; int bt = 0;
#pragma unroll
    for (int t = 1; t < 16; ++t) if (v[t] > bv) { bv = v[t]; bt = t; }
    for (int it = 0; it < KTOP; ++it) {
        float rv = bv; int ri = bt*32 + lane;
#pragma unroll
        for (int off = 16; off; off >>= 1) {
            float ov = __shfl_down_sync(FULLMASK, rv, off);
            int   oi = __shfl_down_sync(FULLMASK, ri, off);
            if (ov > rv || (ov == rv && oi < ri)) { rv = ov; ri = oi; }
        }
        ri = __shfl_sync(FULLMASK, ri, 0);
        if (lane == 0) {
            // flat edge index F = w*20+it; srcT[F&511][F>>9] = flat_topk[F]
            int F = w * KTOP + it;
            g_srcT[(F & 511) * KTOP + (F >> 9)] = ri;
        }
        if ((ri & 31) == lane) {
            int kt = ri >> 5;
#pragma unroll
            for (int t = 0; t < 16; ++t) if (t == kt) v[t] = -INFINITY;
            bv = v[0]; bt = 0;
#pragma unroll
            for (int t = 1; t < 16; ++t) if (v[t] > bv) { bv = v[t]; bt = t; }
        }
    }
    // block 0: emb-side attention dots + fc_w transpose
    if (blockIdx.x == 0) {
        int n = threadIdx.x;                 // 512 threads
        const float* e = emb + n * Dd;
        float es = 0.f, ed = 0.f;
#pragma unroll
        for (int k = 0; k < Dd; ++k) {
            float vv = e[k];
            es = fmaf(vv, attn_w[Dd + k],   es);
            ed = fmaf(vv, attn_w[3*Dd + k], ed);
        }
        g_esrc[n] = es;
        g_edst[n] = ed;
        for (int i = n; i < Dd*Dd; i += 512) {
            int d = i >> 6, f = i & 63;
            g_wT[f*64 + d] = fc_w[i];
        }
    }
}

// ---------------- K4: fused z-GEMM + attention + rst + BN stats ------------
// One CTA per batch b, 1024 threads (32 warps, 50% occupancy target).
__global__ void __launch_bounds__(1024, 1)
k4_fused(const float* __restrict__ data,
         const float* __restrict__ emb,
         const float* __restrict__ attn_w,
         const float* __restrict__ attn_b_p,
         const float* __restrict__ fc_b) {
    extern __shared__ float sm[];
    float* z_sm = sm;                    // 512*65 = 33280
    float* dat  = z_sm + 512*65;         // 256*68 = 17408
    float* wT   = dat + 256*68;          // 4096
    float* ssrc = wT + 4096;             // 512
    float* sdst = ssrc + 512;            // 512
    float* aw   = sdst + 512;            // 256
    float* bias = aw + 256;              // 64
    float* als  = bias + 64;             // 32*40 = 1280 (per-warp alpha/src)
    float* ssum = als + 1280;            // 64
    float* ssq  = ssum + 64;             // 64

    int b = blockIdx.x, tid = threadIdx.x;   // 1024 threads
    int w = tid >> 5, lane = tid & 31;

    if (tid < 256) aw[tid] = attn_w[tid];
    else if (tid < 320) bias[tid-256] = fc_b[tid-256];
    else if (tid < 448) {
        int t = tid - 320;
        if (t < 64) ssum[t] = 0.f; else ssq[t-64] = 0.f;
    }
    for (int i = tid; i < 4096; i += 1024) wT[i] = g_wT[i];

    // ---- z GEMM: 2 chunks x 256 rows; thread = 2 rows x 8 channels ----
    int cg = tid & 7, rp = tid >> 3;         // rp in 0..127
    int r0 = rp*2, r1 = r0 + 1, d0 = cg*8;

    const float4* dg = (const float4*)(data + (size_t)b * Nn * Dd);
    for (int chunk = 0; chunk < 2; ++chunk) {
#pragma unroll
        for (int it = 0; it < 4; ++it) {
            int i4 = tid + it*1024;
            float4 v = dg[chunk*4096 + i4];
            int n = i4 >> 4, f0 = (i4 & 15) << 2;
            *(float4*)&dat[n*68 + f0] = v;
        }
        __syncthreads();

        ull acc[8] = {0,0,0,0,0,0,0,0};  // [0..3] row r0, [4..7] row r1
#pragma unroll 8
        for (int f = 0; f < 64; f += 2) {
            float2 a0 = *(const float2*)&dat[r0*68 + f];
            float2 a1 = *(const float2*)&dat[r1*68 + f];
            const float4* wp0 = (const float4*)&wT[f*64 + d0];
            const float4* wp1 = (const float4*)&wT[(f+1)*64 + d0];
            float4 u0 = wp0[0], u1 = wp0[1];
            float4 v0 = wp1[0], v1 = wp1[1];
            ull q0 = pack2(u0.x,u0.y), q1 = pack2(u0.z,u0.w);
            ull q2 = pack2(u1.x,u1.y), q3 = pack2(u1.z,u1.w);
            ull s0 = pack2(v0.x,v0.y), s1 = pack2(v0.z,v0.w);
            ull s2 = pack2(v1.x,v1.y), s3 = pack2(v1.z,v1.w);
            ull pa0 = pack2(a0.x,a0.x), pb0 = pack2(a0.y,a0.y);
            ull pa1 = pack2(a1.x,a1.x), pb1 = pack2(a1.y,a1.y);
            fma2(acc[0],pa0,q0); fma2(acc[1],pa0,q1);
            fma2(acc[2],pa0,q2); fma2(acc[3],pa0,q3);
            fma2(acc[4],pa1,q0); fma2(acc[5],pa1,q1);
            fma2(acc[6],pa1,q2); fma2(acc[7],pa1,q3);
            fma2(acc[0],pb0,s0); fma2(acc[1],pb0,s1);
            fma2(acc[2],pb0,s2); fma2(acc[3],pb0,s3);
            fma2(acc[4],pb1,s0); fma2(acc[5],pb1,s1);
            fma2(acc[6],pb1,s2); fma2(acc[7],pb1,s3);
        }
        int ng = chunk << 8;
#pragma unroll
        for (int j = 0; j < 4; ++j) {
            float2 va = unpack2(acc[j]);
            float2 vb = unpack2(acc[4+j]);
            float b0 = bias[d0 + 2*j], b1 = bias[d0 + 2*j + 1];
            z_sm[(ng+r0)*65 + d0 + 2*j]     = va.x + b0;
            z_sm[(ng+r0)*65 + d0 + 2*j + 1] = va.y + b1;
            z_sm[(ng+r1)*65 + d0 + 2*j]     = vb.x + b0;
            z_sm[(ng+r1)*65 + d0 + 2*j + 1] = vb.y + b1;
        }
        __syncthreads();
    }

    // ---- s_src / s_dst: 2 threads per node (k halves) ----
    {
        int n = tid >> 1, half = tid & 1, k0 = half * 32;
        float s1 = 0.f, s2 = 0.f;
#pragma unroll
        for (int k = 0; k < 32; ++k) {
            float zv = z_sm[n*65 + k0 + k];
            s1 = fmaf(zv, aw[k0 + k],       s1);
            s2 = fmaf(zv, aw[128 + k0 + k], s2);
        }
        s1 += __shfl_xor_sync(FULLMASK, s1, 1);
        s2 += __shfl_xor_sync(FULLMASK, s2, 1);
        if (half == 0) {
            ssrc[n] = s1 + g_esrc[n];
            sdst[n] = s2 + g_edst[n];
        }
    }
    __syncthreads();

    // ---- attention gather: warp handles 16 dst ----
    const float ab = *attn_b_p;
    float* mybuf = als + w * 40;
    float acc_s0 = 0.f, acc_q0 = 0.f, acc_s1 = 0.f, acc_q1 = 0.f;

    for (int r = 0; r < 16; ++r) {
        int d = w * 16 + r;
        float sd = sdst[d];
        int srcj = 0; float sc = -INFINITY;
        if (lane < KTOP) {
            srcj = g_srcT[d * KTOP + lane];
            float x = ssrc[srcj] + sd + ab;
            sc = (x > 0.f) ? x : NEG_SLOPE * x;
        }
        float m = sc;
#pragma unroll
        for (int off = 16; off; off >>= 1)
            m = fmaxf(m, __shfl_xor_sync(FULLMASK, m, off));
        float p = (lane < KTOP) ? expf(sc - m) : 0.f;
        float ps = p;
#pragma unroll
        for (int off = 16; off; off >>= 1)
            ps += __shfl_xor_sync(FULLMASK, ps, off);
        if (lane < KTOP) {
            mybuf[2*lane]     = p / ps;
            mybuf[2*lane + 1] = __int_as_float(srcj);
        }
        __syncwarp();
        float h0 = 0.f, h1 = 0.f;
#pragma unroll
        for (int j = 0; j < KTOP; ++j) {
            float2 asp = *(const float2*)&mybuf[2*j];
            int s = __float_as_int(asp.y);
            h0 = fmaf(asp.x, z_sm[s*65 + lane],      h0);
            h1 = fmaf(asp.x, z_sm[s*65 + 32 + lane], h1);
        }
        __syncwarp();
        float e0 = emb[d*64 + lane];
        float e1 = emb[d*64 + 32 + lane];
        float r0v = h0 * e0, r1v = h1 * e1;
        size_t ro = ((size_t)b * Nn + d) * Dd;
        g_rst[ro + lane]      = r0v;
        g_rst[ro + 32 + lane] = r1v;
        acc_s0 += r0v; acc_q0 = fmaf(r0v, r0v, acc_q0);
        acc_s1 += r1v; acc_q1 = fmaf(r1v, r1v, acc_q1);
    }
    atomicAdd(&ssum[lane],      acc_s0);
    atomicAdd(&ssum[lane + 32], acc_s1);
    atomicAdd(&ssq[lane],       acc_q0);
    atomicAdd(&ssq[lane + 32],  acc_q1);
    __syncthreads();
    if (tid < 64) {
        atomicAdd(&g_sum[tid],   ssum[tid]);
        atomicAdd(&g_sumsq[tid], ssq[tid]);
    }
}

// ---------------- K6: BN stats + BN + relu + output projection -------------
__global__ void k6_out(const float* __restrict__ gamma,
                       const float* __restrict__ beta,
                       const float* __restrict__ out_w,
                       const float* __restrict__ out_b_p,
                       float* __restrict__ out) {
    __shared__ float sc_s[64], sh_s[64];
    if (threadIdx.x < 64) {
        int t = threadIdx.x;
        const float inv_n = 1.0f / (float)(Bsz * Nn);
        float mu  = g_sum[t] * inv_n;
        float var = g_sumsq[t] * inv_n - mu * mu;
        float s   = gamma[t] / sqrtf(var + BN_EPS);
        sc_s[t] = s;
        sh_s[t] = beta[t] - mu * s;
    }
    __syncthreads();
    int gw   = blockIdx.x * (blockDim.x >> 5) + (threadIdx.x >> 5);
    int lane = threadIdx.x & 31;
    int g = lane >> 4, l16 = lane & 15;
    int row = gw * 2 + g;
    const float4* r4 = (const float4*)(g_rst + (size_t)row * Dd);
    float4 v  = r4[l16];
    float4 sc = *(const float4*)&sc_s[4*l16];
    float4 sh = *(const float4*)&sh_s[4*l16];
    float4 ww = ((const float4*)out_w)[l16];
    float s = fmaxf(fmaf(v.x, sc.x, sh.x), 0.f) * ww.x
            + fmaxf(fmaf(v.y, sc.y, sh.y), 0.f) * ww.y
            + fmaxf(fmaf(v.z, sc.z, sh.z), 0.f) * ww.z
            + fmaxf(fmaf(v.w, sc.w, sh.w), 0.f) * ww.w;
#pragma unroll
    for (int off = 8; off; off >>= 1)
        s += __shfl_xor_sync(FULLMASK, s, off);
    if (l16 == 0) out[row] = s + *out_b_p;
}

// ---------------- launch ----------------------------------------------------
extern "C" void kernel_launch(void* const* d_in, const int* in_sizes, int n_in,
                              void* d_out, int out_size) {
    const float* data     = (const float*)d_in[0];
    const float* emb      = (const float*)d_in[1];
    const float* fc_w     = (const float*)d_in[2];
    const float* fc_b     = (const float*)d_in[3];
    const float* attn_w   = (const float*)d_in[4];
    const float* attn_b   = (const float*)d_in[5];
    const float* bn_gamma = (const float*)d_in[6];
    const float* bn_beta  = (const float*)d_in[7];
    const float* out_w    = (const float*)d_in[8];
    const float* out_b    = (const float*)d_in[9];
    float* out = (float*)d_out;

    const int K4_SMEM = (512*65 + 256*68 + 4096 + 512 + 512 + 256 + 64 + 1280
                         + 64 + 64) * (int)sizeof(float);   // 230144 B
    cudaFuncSetAttribute(k4_fused, cudaFuncAttributeMaxDynamicSharedMemorySize,
                         K4_SMEM);

    k1_cos  <<<dim3(8, 8), 256>>>(emb);
    k2_topk <<<32, 512>>>(emb, attn_w, fc_w);
    k4_fused<<<Bsz, 1024, K4_SMEM>>>(data, emb, attn_w, attn_b, fc_b);
    k6_out  <<<Bsz * Nn / 32, 512>>>(bn_gamma, bn_beta, out_w, out_b, out);
}

// round 5
// speedup vs baseline: 1.4914x; 1.4914x over previous
#include <cuda_runtime.h>
#include <cuda_fp16.h>
#include <math.h>

#define Bsz 128
#define Nn  512
#define Dd  64
#define KTOP 20
#define FULLMASK 0xFFFFFFFFu
#define NEG_SLOPE 0.2f
#define BN_EPS 1e-5f

typedef unsigned long long ull;

// ---------------- scratch (device globals; no allocations) ----------------
__device__ __align__(16) __half2 g_z_h[Bsz*Nn*32];    // z as half2 pairs (8.4MB)
__device__ __align__(16) __half2 g_rst_h[Bsz*Nn*32];  // rst as half2 (8.4MB)
__device__ __align__(16) float g_cos[Nn*Nn];          // 1 MB
__device__ float g_zsrc[Bsz*Nn];                      // z-part of s_src per row
__device__ float g_zdst[Bsz*Nn];
__device__ int   g_srcJ[KTOP*Nn];                     // j-major: srcJ[j][d]
__device__ float g_esrc[Nn];
__device__ float g_edst[Nn];
__device__ __align__(16) float g_sum[Dd];
__device__ __align__(16) float g_sumsq[Dd];

// ---------------- f32x2 packed helpers -------------------------------------
__device__ __forceinline__ ull pack2(float x, float y) {
    ull r; asm("mov.b64 %0, {%1, %2};" : "=l"(r) : "f"(x), "f"(y)); return r;
}
__device__ __forceinline__ void fma2(ull& d, ull a, ull b) {
    asm("fma.rn.f32x2 %0, %1, %2, %0;" : "+l"(d) : "l"(a), "l"(b));
}
__device__ __forceinline__ float2 unpack2(ull v) {
    float2 r; asm("mov.b64 {%0, %1}, %2;" : "=f"(r.x), "=f"(r.y) : "l"(v)); return r;
}

// ===========================================================================
// K1A: blocks 0..63 -> cosine Gram; blocks 64..1087 -> z-GEMM (64-row tiles)
// smem (floats): GEMM branch At[0,4352) wP[4352,8704) aws[8704,8768)
//                awd[8768,8832) bias[8832,8896)  -> 8896 floats = 35,584 B
// ===========================================================================
__global__ void __launch_bounds__(256)
k1a(const float* __restrict__ emb,
    const float* __restrict__ data,
    const float* __restrict__ fc_w,
    const float* __restrict__ fc_b,
    const float* __restrict__ attn_w) {
    extern __shared__ float sm[];
    int tid = threadIdx.x;

    if (blockIdx.x < 64) {
        // -------- cosine branch --------
        float* At = sm;            // 64*68
        float* Bt = sm + 4352;     // 64*68
        float* rni = sm + 8704;    // 64
        float* rnj = rni + 64;     // 64
        int bb = blockIdx.x;
        int i0 = (bb >> 3) * 64, j0 = (bb & 7) * 64;
        for (int idx = tid; idx < 4096; idx += 256) {
            int r = idx >> 6, k = idx & 63;
            At[k*68 + r] = emb[(i0 + r)*64 + k];
            Bt[k*68 + r] = emb[(j0 + r)*64 + k];
        }
        __syncthreads();
        if (tid < 128) {
            int r = tid & 63;
            const float* T = (tid >= 64) ? Bt : At;
            float s = 0.f;
#pragma unroll
            for (int k = 0; k < 64; ++k) { float v = T[k*68 + r]; s = fmaf(v, v, s); }
            float inv = 1.0f / sqrtf(s);
            if (tid >= 64) rnj[r] = inv; else rni[r] = inv;
        } else if (bb == 0) {
            int t = tid - 128;
            if (t < 64) g_sum[t] = 0.f;
            else if (t < 128) g_sumsq[t - 64] = 0.f;
        }
        __syncthreads();
        int tx = tid & 15, ty = tid >> 4;
        int r0 = ty * 4, c0 = tx * 4;
        float acc[4][4] = {};
#pragma unroll 8
        for (int k = 0; k < 64; ++k) {
            float4 a4 = *(const float4*)&At[k*68 + r0];
            float4 b4 = *(const float4*)&Bt[k*68 + c0];
            float av[4] = {a4.x, a4.y, a4.z, a4.w};
            float bv[4] = {b4.x, b4.y, b4.z, b4.w};
#pragma unroll
            for (int r = 0; r < 4; ++r)
#pragma unroll
                for (int c = 0; c < 4; ++c)
                    acc[r][c] = fmaf(av[r], bv[c], acc[r][c]);
        }
        float rj[4];
#pragma unroll
        for (int c = 0; c < 4; ++c) rj[c] = rnj[c0 + c];
#pragma unroll
        for (int r = 0; r < 4; ++r) {
            float ri = rni[r0 + r];
            float4 o;
            o.x = acc[r][0] * ri * rj[0];
            o.y = acc[r][1] * ri * rj[1];
            o.z = acc[r][2] * ri * rj[2];
            o.w = acc[r][3] * ri * rj[3];
            *(float4*)&g_cos[(i0 + r0 + r)*Nn + j0 + c0] = o;
        }
    } else {
        // -------- z-GEMM branch: 64 global rows per CTA, 1024 CTAs --------
        float* At  = sm;                      // 64*68 fp32 (later reused as z_s)
        ull*   wP  = (ull*)(sm + 4352);       // 64*34 packed w pairs (2176 ull)
        float* aws = sm + 8704;               // 64
        float* awd = aws + 64;                // 64
        float* bias= awd + 64;                // 64  (ends at 8896)
        int zb = blockIdx.x - 64;             // 0..1023
        int m0 = zb * 64;                     // global row base

        for (int idx = tid; idx < 4096; idx += 256) {
            int r = idx >> 6, k = idx & 63;
            At[k*68 + r] = data[(m0 + r)*64 + k];
        }
        for (int idx = tid; idx < 2048; idx += 256) {
            int cp = idx >> 6, k = idx & 63;
            float lo = fc_w[(2*cp)*64 + k];
            float hi = fc_w[(2*cp+1)*64 + k];
            wP[k*34 + cp] = pack2(lo, hi);
        }
        if (tid < 64) {
            bias[tid] = fc_b[tid];
            aws[tid]  = attn_w[tid];         // a_src z-part
            awd[tid]  = attn_w[128 + tid];   // a_dst z-part
        }
        __syncthreads();

        int tx = tid & 15, ty = tid >> 4;
        int r0 = ty * 4;                      // local rows r0..r0+3
        ull acc[4][2] = {};
#pragma unroll 8
        for (int k = 0; k < 64; ++k) {
            float4 a4 = *(const float4*)&At[k*68 + r0];
            ulonglong2 w2 = *(const ulonglong2*)&wP[k*34 + 2*tx];
            ull pa0 = pack2(a4.x, a4.x), pa1 = pack2(a4.y, a4.y);
            ull pa2 = pack2(a4.z, a4.z), pa3 = pack2(a4.w, a4.w);
            fma2(acc[0][0], pa0, w2.x); fma2(acc[0][1], pa0, w2.y);
            fma2(acc[1][0], pa1, w2.x); fma2(acc[1][1], pa1, w2.y);
            fma2(acc[2][0], pa2, w2.x); fma2(acc[2][1], pa2, w2.y);
            fma2(acc[3][0], pa3, w2.x); fma2(acc[3][1], pa3, w2.y);
        }
        __syncthreads();     // done reading At; reuse as z_s
        float* z_s = At;
        float b0 = bias[4*tx], b1 = bias[4*tx+1], b2 = bias[4*tx+2], b3 = bias[4*tx+3];
#pragma unroll
        for (int r = 0; r < 4; ++r) {
            float2 v0 = unpack2(acc[r][0]);
            float2 v1 = unpack2(acc[r][1]);
            float z0 = v0.x + b0, z1 = v0.y + b1;
            float z2 = v1.x + b2, z3 = v1.y + b3;
            int row = m0 + r0 + r;
            g_z_h[row*32 + 2*tx]     = __floats2half2_rn(z0, z1);
            g_z_h[row*32 + 2*tx + 1] = __floats2half2_rn(z2, z3);
            float* zp = &z_s[(r0 + r)*68 + 4*tx];
            zp[0] = z0; zp[1] = z1; zp[2] = z2; zp[3] = z3;
        }
        __syncthreads();
        if (tid < 128) {
            int n = tid >> 1, half = tid & 1, k0 = half * 32;
            float s1 = 0.f, s2 = 0.f;
#pragma unroll
            for (int k = 0; k < 32; ++k) {
                float zv = z_s[n*68 + k0 + k];
                s1 = fmaf(zv, aws[k0 + k], s1);
                s2 = fmaf(zv, awd[k0 + k], s2);
            }
            s1 += __shfl_xor_sync(FULLMASK, s1, 1);
            s2 += __shfl_xor_sync(FULLMASK, s2, 1);
            if (half == 0) {
                g_zsrc[m0 + n] = s1;
                g_zdst[m0 + n] = s2;
            }
        }
    }
}

// ===========================================================================
// K2: per-row top-20 (warp per row, 128 CTAs) + emb-side dots in block 0
// ===========================================================================
__global__ void __launch_bounds__(128)
k2_topk(const float* __restrict__ emb,
        const float* __restrict__ attn_w) {
    int w    = blockIdx.x * 4 + (threadIdx.x >> 5);   // row 0..511
    int lane = threadIdx.x & 31;
    const float* row = g_cos + w * Nn;
    float v[16];
#pragma unroll
    for (int t = 0; t < 16; ++t) v[t] = row[t*32 + lane];
    float bv = v[0]; int bt = 0;
#pragma unroll
    for (int t = 1; t < 16; ++t) if (v[t] > bv) { bv = v[t]; bt = t; }
    for (int it = 0; it < KTOP; ++it) {
        float rv = bv; int ri = bt*32 + lane;
#pragma unroll
        for (int off = 16; off; off >>= 1) {
            float ov = __shfl_down_sync(FULLMASK, rv, off);
            int   oi = __shfl_down_sync(FULLMASK, ri, off);
            if (ov > rv || (ov == rv && oi < ri)) { rv = ov; ri = oi; }
        }
        ri = __shfl_sync(FULLMASK, ri, 0);
        if (lane == 0) {
            int F = w * KTOP + it;                    // flat edge id
            g_srcJ[(F >> 9) * Nn + (F & 511)] = ri;   // j-major
        }
        if ((ri & 31) == lane) {
            int kt = ri >> 5;
#pragma unroll
            for (int t = 0; t < 16; ++t) if (t == kt) v[t] = -INFINITY;
            bv = v[0]; bt = 0;
#pragma unroll
            for (int t = 1; t < 16; ++t) if (v[t] > bv) { bv = v[t]; bt = t; }
        }
    }
    if (blockIdx.x == 0) {
        for (int n = threadIdx.x; n < Nn; n += 128) {
            const float* e = emb + n * Dd;
            float es = 0.f, ed = 0.f;
#pragma unroll
            for (int k = 0; k < Dd; ++k) {
                float vv = e[k];
                es = fmaf(vv, attn_w[Dd + k],   es);
                ed = fmaf(vv, attn_w[3*Dd + k], ed);
            }
            g_esrc[n] = es;
            g_edst[n] = ed;
        }
    }
}

// ===========================================================================
// KB: attention per batch. 1024 threads. z in smem as half2; shfl-free softmax.
// ===========================================================================
__global__ void __launch_bounds__(1024, 1)
kb_attn(const float* __restrict__ emb,
        const float* __restrict__ attn_b_p) {
    extern __shared__ char smc[];
    float2*  als  = (float2*)smc;                      // 512*20   (81,920B)
    __half2* z_h  = (__half2*)(smc + 81920);           // 512*33   (67,584B)
    float*   ssrc = (float*)(smc + 149504);            // 512
    float*   sdst = (float*)(smc + 151552);            // 512
    // after gather, als region is reused for stats partials:
    float*   wbufS = (float*)smc;                      // 32*66
    float*   wbufQ = (float*)(smc + 8448);             // 32*66

    int b = blockIdx.x, tid = threadIdx.x;
    int w = tid >> 5, lane = tid & 31;

    // stage z[b] (half2) into smem, padded stride 33
    {
        const uint4* zg = (const uint4*)(g_z_h + (size_t)b * Nn * 32);
        uint* zu = (uint*)z_h;
#pragma unroll
        for (int it = 0; it < 4; ++it) {
            int i = tid + it * 1024;            // uint4 index, 4096 total
            uint4 v = zg[i];
            int n = i >> 3, c0 = (i & 7) * 4;
            uint* p = zu + n*33 + c0;
            p[0] = v.x; p[1] = v.y; p[2] = v.z; p[3] = v.w;
        }
    }
    if (tid < 512) {
        ssrc[tid] = g_zsrc[b*Nn + tid] + g_esrc[tid];
        sdst[tid] = g_zdst[b*Nn + tid] + g_edst[tid];
    }
    __syncthreads();

    // ---- scores + softmax: 2 threads per dst, 10 edges each, regs only ----
    {
        const float ab = *attn_b_p;
        int d = tid >> 1, half = tid & 1;
        float sd = sdst[d];
        float sc[10]; int si[10];
#pragma unroll
        for (int j10 = 0; j10 < 10; ++j10) {
            int j = half * 10 + j10;
            int s = g_srcJ[j * Nn + d];
            si[j10] = s;
            float x = ssrc[s] + sd + ab;
            sc[j10] = (x > 0.f) ? x : NEG_SLOPE * x;
        }
        float m = sc[0];
#pragma unroll
        for (int j10 = 1; j10 < 10; ++j10) m = fmaxf(m, sc[j10]);
        m = fmaxf(m, __shfl_xor_sync(FULLMASK, m, 1));
        float p[10], ps = 0.f;
#pragma unroll
        for (int j10 = 0; j10 < 10; ++j10) { p[j10] = expf(sc[j10] - m); ps += p[j10]; }
        float denom = ps + __shfl_xor_sync(FULLMASK, ps, 1);
        float inv = 1.0f / denom;
#pragma unroll
        for (int j10 = 0; j10 < 10; ++j10) {
            int j = half * 10 + j10;
            als[d*KTOP + j] = make_float2(p[j10] * inv, __int_as_float(si[j10]));
        }
    }
    __syncthreads();

    // ---- gather: warp per dst (16 dst per warp), lane = channel pair ----
    float acc_s0 = 0.f, acc_q0 = 0.f, acc_s1 = 0.f, acc_q1 = 0.f;
    for (int r = 0; r < 16; ++r) {
        int d = w * 16 + r;
        float h0 = 0.f, h1 = 0.f;
#pragma unroll
        for (int jj = 0; jj < 10; ++jj) {
            float4 q = *(const float4*)&als[d*KTOP + jj*2];
            int s0 = __float_as_int(q.y);
            int s1 = __float_as_int(q.w);
            float2 fa = __half22float2(z_h[s0*33 + lane]);
            float2 fb = __half22float2(z_h[s1*33 + lane]);
            h0 = fmaf(q.x, fa.x, h0); h1 = fmaf(q.x, fa.y, h1);
            h0 = fmaf(q.z, fb.x, h0); h1 = fmaf(q.z, fb.y, h1);
        }
        float2 e2 = *(const float2*)&emb[d*64 + 2*lane];
        float r0v = h0 * e2.x, r1v = h1 * e2.y;
        g_rst_h[((size_t)b*Nn + d)*32 + lane] = __floats2half2_rn(r0v, r1v);
        acc_s0 += r0v; acc_q0 = fmaf(r0v, r0v, acc_q0);
        acc_s1 += r1v; acc_q1 = fmaf(r1v, r1v, acc_q1);
    }
    __syncthreads();                      // als reads done; reuse region
    wbufS[w*66 + 2*lane]     = acc_s0;
    wbufS[w*66 + 2*lane + 1] = acc_s1;
    wbufQ[w*66 + 2*lane]     = acc_q0;
    wbufQ[w*66 + 2*lane + 1] = acc_q1;
    __syncthreads();
    if (tid < 64) {
        float s = 0.f, q = 0.f;
#pragma unroll 8
        for (int ww = 0; ww < 32; ++ww) {
            s += wbufS[ww*66 + tid];
            q += wbufQ[ww*66 + tid];
        }
        atomicAdd(&g_sum[tid],   s);
        atomicAdd(&g_sumsq[tid], q);
    }
}

// ===========================================================================
// K6: BN stats finalize + BN + relu + output projection (reads fp16 rst)
// ===========================================================================
__global__ void __launch_bounds__(256)
k6_out(const float* __restrict__ gamma,
       const float* __restrict__ beta,
       const float* __restrict__ out_w,
       const float* __restrict__ out_b_p,
       float* __restrict__ out) {
    __shared__ float sc_s[64], sh_s[64], wv[64];
    if (threadIdx.x < 64) {
        int t = threadIdx.x;
        const float inv_n = 1.0f / (float)(Bsz * Nn);
        float mu  = g_sum[t] * inv_n;
        float var = g_sumsq[t] * inv_n - mu * mu;
        float s   = gamma[t] / sqrtf(var + BN_EPS);
        sc_s[t] = s;
        sh_s[t] = beta[t] - mu * s;
        wv[t]   = out_w[t];
    }
    __syncthreads();
    // warp handles 8 rows; 4 lanes per row, 16 channels per lane
    int warp = blockIdx.x * 8 + (threadIdx.x >> 5);
    int lane = threadIdx.x & 31;
    int row  = warp * 8 + (lane >> 2);
    int q    = lane & 3;                  // channel block 16q..16q+15
    const uint4* rp = (const uint4*)(g_rst_h + (size_t)row * 32 + q * 8);
    uint4 u0 = rp[0], u1 = rp[1];
    uint uu[8] = {u0.x, u0.y, u0.z, u0.w, u1.x, u1.y, u1.z, u1.w};
    float s = 0.f;
#pragma unroll
    for (int t = 0; t < 8; ++t) {
        float2 f = __half22float2(*(__half2*)&uu[t]);
        int ch = q*16 + 2*t;
        float a = fmaxf(fmaf(f.x, sc_s[ch],   sh_s[ch]),   0.f) * wv[ch];
        float bq = fmaxf(fmaf(f.y, sc_s[ch+1], sh_s[ch+1]), 0.f) * wv[ch+1];
        s += a + bq;
    }
    s += __shfl_xor_sync(FULLMASK, s, 1);
    s += __shfl_xor_sync(FULLMASK, s, 2);
    if (q == 0) out[row] = s + *out_b_p;
}

// ---------------- launch ----------------------------------------------------
extern "C" void kernel_launch(void* const* d_in, const int* in_sizes, int n_in,
                              void* d_out, int out_size) {
    const float* data     = (const float*)d_in[0];
    const float* emb      = (const float*)d_in[1];
    const float* fc_w     = (const float*)d_in[2];
    const float* fc_b     = (const float*)d_in[3];
    const float* attn_w   = (const float*)d_in[4];
    const float* attn_b   = (const float*)d_in[5];
    const float* bn_gamma = (const float*)d_in[6];
    const float* bn_beta  = (const float*)d_in[7];
    const float* out_w    = (const float*)d_in[8];
    const float* out_b    = (const float*)d_in[9];
    float* out = (float*)d_out;

    const int K1A_SMEM = 8896 * (int)sizeof(float);          // 35,584 B
    const int KB_SMEM  = 153600;                              // bytes
    cudaFuncSetAttribute(kb_attn, cudaFuncAttributeMaxDynamicSharedMemorySize,
                         KB_SMEM);

    k1a     <<<64 + 1024, 256, K1A_SMEM>>>(emb, data, fc_w, fc_b, attn_w);
    k2_topk <<<128, 128>>>(emb, attn_w);
    kb_attn <<<Bsz, 1024, KB_SMEM>>>(emb, attn_b);
    k6_out  <<<Bsz * Nn / 64, 256>>>(bn_gamma, bn_beta, out_w, out_b, out);
}